// round 6
// baseline (speedup 1.0000x reference)
#include <cuda_runtime.h>

// out[v] = sum over edges (u->v) of emb[u].  D_FEAT = 64 fp32.
// CSR-by-dst built in-graph, then atomic-free pull-mode sum.
// L2 traffic budget: ~25MB prep + 320MB gather + 12.8MB write  (vs 640MB for
// the push/atomic kernel) -> ~30us floor at the ~6300 B/cyc LTS cap.

#define N_NODES_MAX 50000
#define N_EDGES_MAX 1250000
#define D_FEAT 64
#define VEC_PER_ROW 16  // 64 floats / 4

__device__ int g_deg[N_NODES_MAX];
__device__ int g_off[N_NODES_MAX + 1];
__device__ int g_pos[N_NODES_MAX];
__device__ int g_perm[N_EDGES_MAX];

__global__ void zero_deg_kernel(int n_nodes) {
    int i = blockIdx.x * blockDim.x + threadIdx.x;
    if (i < n_nodes) g_deg[i] = 0;
}

// 4 edges per thread, int4 load, 4 independent atomic chains.
__global__ void hist_kernel(const int* __restrict__ dst, int n_edges) {
    int q = blockIdx.x * blockDim.x + threadIdx.x;
    int e0 = q * 4;
    if (e0 + 3 < n_edges) {
        int4 d = __ldg((const int4*)(dst + e0));
        atomicAdd(&g_deg[d.x], 1);
        atomicAdd(&g_deg[d.y], 1);
        atomicAdd(&g_deg[d.z], 1);
        atomicAdd(&g_deg[d.w], 1);
    } else {
        for (int e = e0; e < n_edges; e++) atomicAdd(&g_deg[dst[e]], 1);
    }
}

// Single-block exclusive scan over n_nodes (<=50K) degrees.
__global__ void scan_kernel(int n_nodes) {
    const int T = 1024;
    int tid = threadIdx.x;
    int chunk = (n_nodes + T - 1) / T;
    int base = tid * chunk;

    int sum = 0;
#pragma unroll 8
    for (int i = 0; i < chunk; i++) {
        int idx = base + i;
        if (idx < n_nodes) sum += g_deg[idx];
    }

    __shared__ int s[T];
    s[tid] = sum;
    __syncthreads();
    for (int off = 1; off < T; off <<= 1) {
        int v = (tid >= off) ? s[tid - off] : 0;
        __syncthreads();
        s[tid] += v;
        __syncthreads();
    }
    int run = s[tid] - sum;  // exclusive prefix of this thread's chunk

#pragma unroll 4
    for (int i = 0; i < chunk; i++) {
        int idx = base + i;
        if (idx < n_nodes) {
            g_off[idx] = run;
            g_pos[idx] = run;
            run += g_deg[idx];
        }
    }
    if (tid == T - 1) g_off[n_nodes] = s[T - 1];
}

// 4 edges per thread, int4 loads, 4 independent atomicAdd->STG chains.
__global__ void scatter_kernel(const int* __restrict__ src,
                               const int* __restrict__ dst, int n_edges) {
    int q = blockIdx.x * blockDim.x + threadIdx.x;
    int e0 = q * 4;
    if (e0 + 3 < n_edges) {
        int4 s = __ldg((const int4*)(src + e0));
        int4 d = __ldg((const int4*)(dst + e0));
        int p0 = atomicAdd(&g_pos[d.x], 1);
        int p1 = atomicAdd(&g_pos[d.y], 1);
        int p2 = atomicAdd(&g_pos[d.z], 1);
        int p3 = atomicAdd(&g_pos[d.w], 1);
        g_perm[p0] = s.x;
        g_perm[p1] = s.y;
        g_perm[p2] = s.z;
        g_perm[p3] = s.w;
    } else {
        for (int e = e0; e < n_edges; e++) {
            int p = atomicAdd(&g_pos[dst[e]], 1);
            g_perm[p] = src[e];
        }
    }
}

// 16 threads per node; each owns one float4 chunk of the 256B row.
// 4 independent accumulators -> 4 overlapped gather chains.
__global__ void node_sum_kernel(const float4* __restrict__ emb,
                                float4* __restrict__ out, int n_nodes) {
    int t = blockIdx.x * blockDim.x + threadIdx.x;
    int node = t >> 4;
    int c = t & 15;
    if (node >= n_nodes) return;

    int beg = g_off[node];
    int end = g_off[node + 1];

    float4 acc0 = make_float4(0.f, 0.f, 0.f, 0.f);
    float4 acc1 = make_float4(0.f, 0.f, 0.f, 0.f);
    float4 acc2 = make_float4(0.f, 0.f, 0.f, 0.f);
    float4 acc3 = make_float4(0.f, 0.f, 0.f, 0.f);

    int j = beg;
    for (; j + 4 <= end; j += 4) {
        int s0 = __ldg(&g_perm[j + 0]);
        int s1 = __ldg(&g_perm[j + 1]);
        int s2 = __ldg(&g_perm[j + 2]);
        int s3 = __ldg(&g_perm[j + 3]);
        float4 a = __ldg(&emb[s0 * VEC_PER_ROW + c]);
        float4 b = __ldg(&emb[s1 * VEC_PER_ROW + c]);
        float4 d = __ldg(&emb[s2 * VEC_PER_ROW + c]);
        float4 e = __ldg(&emb[s3 * VEC_PER_ROW + c]);
        acc0.x += a.x; acc0.y += a.y; acc0.z += a.z; acc0.w += a.w;
        acc1.x += b.x; acc1.y += b.y; acc1.z += b.z; acc1.w += b.w;
        acc2.x += d.x; acc2.y += d.y; acc2.z += d.z; acc2.w += d.w;
        acc3.x += e.x; acc3.y += e.y; acc3.z += e.z; acc3.w += e.w;
    }
    for (; j < end; j++) {
        float4 a = __ldg(&emb[__ldg(&g_perm[j]) * VEC_PER_ROW + c]);
        acc0.x += a.x; acc0.y += a.y; acc0.z += a.z; acc0.w += a.w;
    }

    float4 r;
    r.x = (acc0.x + acc1.x) + (acc2.x + acc3.x);
    r.y = (acc0.y + acc1.y) + (acc2.y + acc3.y);
    r.z = (acc0.z + acc1.z) + (acc2.z + acc3.z);
    r.w = (acc0.w + acc1.w) + (acc2.w + acc3.w);
    out[node * VEC_PER_ROW + c] = r;
}

extern "C" void kernel_launch(void* const* d_in, const int* in_sizes, int n_in,
                              void* d_out, int out_size) {
    const float4* emb = (const float4*)d_in[0];
    const int*    src = (const int*)d_in[1];
    const int*    dst = (const int*)d_in[2];

    int n_edges = in_sizes[1];
    int n_nodes = out_size / D_FEAT;

    int n_quads = (n_edges + 3) / 4;
    int qb = (n_quads + 255) / 256;
    int nb = (n_nodes + 255) / 256;

    zero_deg_kernel<<<nb, 256>>>(n_nodes);
    hist_kernel<<<qb, 256>>>(dst, n_edges);
    scan_kernel<<<1, 1024>>>(n_nodes);
    scatter_kernel<<<qb, 256>>>(src, dst, n_edges);

    int tot = n_nodes * 16;
    node_sum_kernel<<<(tot + 255) / 256, 256>>>(emb, (float4*)d_out, n_nodes);
}

// round 9
// speedup vs baseline: 2.2161x; 2.2161x over previous
#include <cuda_runtime.h>
#include <cuda_fp16.h>

// out[v] = sum over edges (u->v) of emb[u], D_FEAT = 64 fp32.
// Phase 1: convert emb fp32 -> fp16 table (halves gather traffic: 256B->128B/row).
// Phase 2: edge-parallel push, 16 threads per EDGE QUAD; each thread owns one
//          8B (4-half) chunk of the 128B row for 4 edges, converts to fp32,
//          and scatters with red.global.add.v4.f32 (fp32 accumulation).
// L2 traffic: ~19MB convert + 160MB gather + 320MB RED + 10MB idx ~= 490MB
// vs 640MB for the all-fp32 push -> expect ~0.77x duration at the LTS cap.

#define N_NODES_MAX 50000
#define D_FEAT 64

__device__ __half g_embh[N_NODES_MAX * D_FEAT];

// Convert 8 floats -> 8 halves per thread (two float4 loads, one uint4 store).
__global__ void convert_kernel(const float4* __restrict__ emb, int n_elems) {
    int i = blockIdx.x * blockDim.x + threadIdx.x;  // i indexes groups of 8 floats
    int base = i * 8;
    if (base >= n_elems) return;
    float4 a = __ldg(&emb[i * 2 + 0]);
    float4 b = __ldg(&emb[i * 2 + 1]);
    __half2 h0 = __floats2half2_rn(a.x, a.y);
    __half2 h1 = __floats2half2_rn(a.z, a.w);
    __half2 h2 = __floats2half2_rn(b.x, b.y);
    __half2 h3 = __floats2half2_rn(b.z, b.w);
    uint4 packed;
    packed.x = *reinterpret_cast<unsigned int*>(&h0);
    packed.y = *reinterpret_cast<unsigned int*>(&h1);
    packed.z = *reinterpret_cast<unsigned int*>(&h2);
    packed.w = *reinterpret_cast<unsigned int*>(&h3);
    reinterpret_cast<uint4*>(g_embh)[i] = packed;
}

__device__ __forceinline__ void red_add_v4(float* p, float x, float y, float z, float w) {
    asm volatile("red.global.add.v4.f32 [%0], {%1, %2, %3, %4};"
                 :: "l"(p), "f"(x), "f"(y), "f"(z), "f"(w) : "memory");
}

__device__ __forceinline__ float4 load_half4_as_float4(const __half* row, int c) {
    uint2 v = __ldg(reinterpret_cast<const uint2*>(row) + c);  // 4 halves
    __half2 h0 = *reinterpret_cast<__half2*>(&v.x);
    __half2 h1 = *reinterpret_cast<__half2*>(&v.y);
    float2 f0 = __half22float2(h0);
    float2 f1 = __half22float2(h1);
    return make_float4(f0.x, f0.y, f1.x, f1.y);
}

__global__ void edge_scatter_half_kernel(const int* __restrict__ src,
                                         const int* __restrict__ dst,
                                         float* __restrict__ out,
                                         int n_edges) {
    long long t = (long long)blockIdx.x * blockDim.x + threadIdx.x;
    int q = (int)(t >> 4);     // edge-quad index
    int c = (int)(t & 15);     // 4-half chunk within the 64-half row
    int e0 = q * 4;
    if (e0 >= n_edges) return;

    if (e0 + 3 < n_edges) {
        int4 s = __ldg((const int4*)(src + e0));
        int4 d = __ldg((const int4*)(dst + e0));

        // 4 independent gather chains (overlap L2 latency)
        float4 v0 = load_half4_as_float4(g_embh + (long long)s.x * D_FEAT, c);
        float4 v1 = load_half4_as_float4(g_embh + (long long)s.y * D_FEAT, c);
        float4 v2 = load_half4_as_float4(g_embh + (long long)s.z * D_FEAT, c);
        float4 v3 = load_half4_as_float4(g_embh + (long long)s.w * D_FEAT, c);

        red_add_v4(out + ((long long)d.x * D_FEAT + c * 4), v0.x, v0.y, v0.z, v0.w);
        red_add_v4(out + ((long long)d.y * D_FEAT + c * 4), v1.x, v1.y, v1.z, v1.w);
        red_add_v4(out + ((long long)d.z * D_FEAT + c * 4), v2.x, v2.y, v2.z, v2.w);
        red_add_v4(out + ((long long)d.w * D_FEAT + c * 4), v3.x, v3.y, v3.z, v3.w);
    } else {
        for (int e = e0; e < n_edges; e++) {
            int s = src[e];
            int d = dst[e];
            float4 v = load_half4_as_float4(g_embh + (long long)s * D_FEAT, c);
            red_add_v4(out + ((long long)d * D_FEAT + c * 4), v.x, v.y, v.z, v.w);
        }
    }
}

extern "C" void kernel_launch(void* const* d_in, const int* in_sizes, int n_in,
                              void* d_out, int out_size) {
    const float4* emb = (const float4*)d_in[0];
    const int*    src = (const int*)d_in[1];
    const int*    dst = (const int*)d_in[2];
    float* out = (float*)d_out;

    int n_elems = in_sizes[0];   // n_nodes * 64 floats
    int n_edges = in_sizes[1];

    // Zero the poisoned output (async memset is graph-capturable).
    cudaMemsetAsync(d_out, 0, (size_t)out_size * sizeof(float));

    int n_grp8 = n_elems / 8;    // D_FEAT=64 divisible by 8
    convert_kernel<<<(n_grp8 + 255) / 256, 256>>>(emb, n_elems);

    int n_quads = (n_edges + 3) / 4;
    long long total_threads = (long long)n_quads * 16;
    int block = 256;
    int grid = (int)((total_threads + block - 1) / block);
    edge_scatter_half_kernel<<<grid, block>>>(src, dst, out, n_edges);
}

// round 10
// speedup vs baseline: 3.1121x; 1.4043x over previous
#include <cuda_runtime.h>
#include <cuda_fp16.h>

// out[v] = sum over edges (u->v) of emb[u], D_FEAT = 64 fp32.
// R10: fp16 everywhere on the hot path.
//  k1 (fused): zero 4 fp16 replica accumulators + convert emb fp32->fp16.
//  k2: edge-parallel push. 8 threads per EDGE QUAD; thread owns one 16B
//      (8-half) chunk for 4 edges; gathers uint4 from fp16 table and scatters
//      with red.global.add.noftz.v4.f16x2 into replica (edge & 3).
//      Replicas shorten each fp16 accumulation chain ~25 -> ~6 adds.
//  k3: combine 4 fp16 replicas -> fp32 out (writes every element; no memset).
// Effective LTS traffic ~573MB vs 800MB for R9 (RMW counted 2x).

#define N_NODES_MAX 50000
#define D_FEAT 64
#define N_REP 4

__device__ __half g_embh[N_NODES_MAX * D_FEAT];
__device__ __half g_acc[N_REP][N_NODES_MAX * D_FEAT];

// i in [0, n_zero16): zero one uint4 (8 halves) of g_acc.
// i in [0, n_conv):  also convert 8 floats -> 8 halves of g_embh.
__global__ void prep_kernel(const float4* __restrict__ emb, int n_conv, int n_zero16) {
    int i = blockIdx.x * blockDim.x + threadIdx.x;
    if (i < n_zero16) {
        reinterpret_cast<uint4*>(g_acc)[i] = make_uint4(0u, 0u, 0u, 0u);
    }
    if (i < n_conv) {
        float4 a = __ldg(&emb[i * 2 + 0]);
        float4 b = __ldg(&emb[i * 2 + 1]);
        __half2 h0 = __floats2half2_rn(a.x, a.y);
        __half2 h1 = __floats2half2_rn(a.z, a.w);
        __half2 h2 = __floats2half2_rn(b.x, b.y);
        __half2 h3 = __floats2half2_rn(b.z, b.w);
        uint4 packed;
        packed.x = *reinterpret_cast<unsigned int*>(&h0);
        packed.y = *reinterpret_cast<unsigned int*>(&h1);
        packed.z = *reinterpret_cast<unsigned int*>(&h2);
        packed.w = *reinterpret_cast<unsigned int*>(&h3);
        reinterpret_cast<uint4*>(g_embh)[i] = packed;
    }
}

__device__ __forceinline__ void red_add_v4h2(__half* p, uint4 v) {
    asm volatile("red.global.add.noftz.v4.f16x2 [%0], {%1, %2, %3, %4};"
                 :: "l"(p), "r"(v.x), "r"(v.y), "r"(v.z), "r"(v.w) : "memory");
}

__global__ void edge_scatter_h2_kernel(const int* __restrict__ src,
                                       const int* __restrict__ dst,
                                       int n_edges) {
    long long t = (long long)blockIdx.x * blockDim.x + threadIdx.x;
    int q = (int)(t >> 3);     // edge-quad index
    int c = (int)(t & 7);      // 16B (8-half) chunk within the 128B row
    int e0 = q * 4;
    if (e0 >= n_edges) return;

    const uint4* tbl = reinterpret_cast<const uint4*>(g_embh);

    if (e0 + 3 < n_edges) {
        int4 s = __ldg((const int4*)(src + e0));
        int4 d = __ldg((const int4*)(dst + e0));

        // 4 independent gather chains (16B each), overlap L2 latency.
        uint4 v0 = __ldg(tbl + (long long)s.x * 8 + c);
        uint4 v1 = __ldg(tbl + (long long)s.y * 8 + c);
        uint4 v2 = __ldg(tbl + (long long)s.z * 8 + c);
        uint4 v3 = __ldg(tbl + (long long)s.w * 8 + c);

        // edge e0+i -> replica i
        red_add_v4h2(g_acc[0] + ((long long)d.x * D_FEAT + c * 8), v0);
        red_add_v4h2(g_acc[1] + ((long long)d.y * D_FEAT + c * 8), v1);
        red_add_v4h2(g_acc[2] + ((long long)d.z * D_FEAT + c * 8), v2);
        red_add_v4h2(g_acc[3] + ((long long)d.w * D_FEAT + c * 8), v3);
    } else {
        for (int e = e0; e < n_edges; e++) {
            int s = src[e];
            int d = dst[e];
            uint4 v = __ldg(tbl + (long long)s * 8 + c);
            red_add_v4h2(g_acc[e & 3] + ((long long)d * D_FEAT + c * 8), v);
        }
    }
}

// out fp32 = sum of 4 fp16 replicas.  Thread handles 8 floats (one uint4 of
// halves per replica, two float4 stores).
__global__ void combine_kernel(float4* __restrict__ out, int n_grp8) {
    int i = blockIdx.x * blockDim.x + threadIdx.x;
    if (i >= n_grp8) return;

    float acc[8];
#pragma unroll
    for (int k = 0; k < 8; k++) acc[k] = 0.f;

#pragma unroll
    for (int r = 0; r < N_REP; r++) {
        uint4 v = __ldg(reinterpret_cast<const uint4*>(g_acc[r]) + i);
        const unsigned int w[4] = {v.x, v.y, v.z, v.w};
#pragma unroll
        for (int k = 0; k < 4; k++) {
            __half2 h = *reinterpret_cast<const __half2*>(&w[k]);
            float2 f = __half22float2(h);
            acc[2 * k + 0] += f.x;
            acc[2 * k + 1] += f.y;
        }
    }

    out[i * 2 + 0] = make_float4(acc[0], acc[1], acc[2], acc[3]);
    out[i * 2 + 1] = make_float4(acc[4], acc[5], acc[6], acc[7]);
}

extern "C" void kernel_launch(void* const* d_in, const int* in_sizes, int n_in,
                              void* d_out, int out_size) {
    const float4* emb = (const float4*)d_in[0];
    const int*    src = (const int*)d_in[1];
    const int*    dst = (const int*)d_in[2];

    int n_elems = in_sizes[0];            // n_nodes * 64 floats
    int n_edges = in_sizes[1];
    int n_nodes = out_size / D_FEAT;

    int n_conv   = n_elems / 8;           // uint4 groups to convert
    int n_zero16 = (n_nodes * D_FEAT * N_REP) / 8;  // uint4 groups to zero
    int n_prep   = n_zero16 > n_conv ? n_zero16 : n_conv;

    prep_kernel<<<(n_prep + 255) / 256, 256>>>(emb, n_conv, n_zero16);

    int n_quads = (n_edges + 3) / 4;
    long long total_threads = (long long)n_quads * 8;
    int grid = (int)((total_threads + 255) / 256);
    edge_scatter_h2_kernel<<<grid, 256>>>(src, dst, n_edges);

    int n_grp8 = out_size / 8;
    combine_kernel<<<(n_grp8 + 255) / 256, 256>>>((float4*)d_out, n_grp8);
}